// round 16
// baseline (speedup 1.0000x reference)
#include <cuda_runtime.h>
#include <cuda_fp16.h>
#include <cstdint>
#include <cstddef>
#include <math.h>

// Problem constants (fixed by setup_inputs)
constexpr int cB = 2, cL = 2048, cD = 256, cP = 16, cK = 4, cI = 3;
constexpr int cF = 32;
constexpr int cKD = 1024;
constexpr int cH = 512;
constexpr int cCH = 64;
constexpr int cNC = cL / cCH;
constexpr int cM = cB * cL;
#define PI_F 3.14159265358979323846f

// ---------------- scratch ---------------------------------------------------
__device__ float g_V[cM * cD];
__device__ float g_Mfeat[cB * cK * cL * cF];
__device__ float g_Qfeat[cB * cK * cL * cF];
__device__ float g_state[cB * cK * cNC * cF * cD];
__device__ float g_comb[cM * cKD];
__device__ float g_acc[cM * cD];
__device__ float g_q0[cM * cD];
__device__ float g_q1[cM * cD];
// half activation buffers
__device__ __half g_xh[cM * cD];
__device__ __half g_Clh[cM * cKD];
__device__ __half g_Hhh[cM * cH];
__device__ __half g_Rfh[cM * cD];
__device__ __half g_q0h[cM * cD];
__device__ __half g_q1h[cM * cD];
__device__ __half g_Alh[cM * cD];
// half weights
__device__ __half g_valwh[cD * cD];
__device__ __half g_r1wh[cI * cH * cKD];
__device__ __half g_r2wh[cI * cD * cH];
__device__ __half g_quwh[cI * cD * cH];
__device__ __half g_outwh[cD * cD];

// ---------------- helpers ---------------------------------------------------
__device__ __forceinline__ uint32_t f2tf(float x) {
    uint32_t r;
    asm("cvt.rna.tf32.f32 %0, %1;" : "=r"(r) : "f"(x));
    return r;
}
__device__ __forceinline__ void mma_tf32(float* c, const uint32_t* a, const uint32_t* b) {
    asm volatile(
        "mma.sync.aligned.m16n8k8.row.col.f32.tf32.tf32.f32 "
        "{%0,%1,%2,%3}, {%4,%5,%6,%7}, {%8,%9}, {%0,%1,%2,%3};\n"
        : "+f"(c[0]), "+f"(c[1]), "+f"(c[2]), "+f"(c[3])
        : "r"(a[0]), "r"(a[1]), "r"(a[2]), "r"(a[3]), "r"(b[0]), "r"(b[1]));
}
__device__ __forceinline__ void mma_f16(float* c, const uint32_t* a, const uint32_t* b) {
    asm volatile(
        "mma.sync.aligned.m16n8k16.row.col.f32.f16.f16.f32 "
        "{%0,%1,%2,%3}, {%4,%5,%6,%7}, {%8,%9}, {%0,%1,%2,%3};\n"
        : "+f"(c[0]), "+f"(c[1]), "+f"(c[2]), "+f"(c[3])
        : "r"(a[0]), "r"(a[1]), "r"(a[2]), "r"(a[3]), "r"(b[0]), "r"(b[1]));
}
__device__ __forceinline__ void cp_async16(void* smem_dst, const void* gsrc) {
    uint32_t s = (uint32_t)__cvta_generic_to_shared(smem_dst);
    asm volatile("cp.async.cg.shared.global [%0], [%1], 16;\n" :: "r"(s), "l"(gsrc));
}
__device__ __forceinline__ void ldsm_x4(uint32_t& r0, uint32_t& r1, uint32_t& r2,
                                        uint32_t& r3, const void* p) {
    uint32_t addr = (uint32_t)__cvta_generic_to_shared(p);
    asm volatile("ldmatrix.sync.aligned.m8n8.x4.shared.b16 {%0,%1,%2,%3}, [%4];\n"
        : "=r"(r0), "=r"(r1), "=r"(r2), "=r"(r3) : "r"(addr));
}

// ---------------- weight / x fp32->fp16 conversion (once per call) ----------
__global__ __launch_bounds__(256) void cvt_h_k(
    const float* __restrict__ val_w, const float* __restrict__ r1w,
    const float* __restrict__ r2w, const float* __restrict__ quw,
    const float* __restrict__ outw, const float* __restrict__ x)
{
    int gsz = gridDim.x * blockDim.x;
    int t0 = blockIdx.x * blockDim.x + threadIdx.x;
    for (int i = t0; i < cD * cD; i += gsz) g_valwh[i] = __float2half(val_w[i]);
    for (int i = t0; i < cI * cH * cKD; i += gsz) g_r1wh[i] = __float2half(r1w[i]);
    for (int i = t0; i < cI * cD * cH; i += gsz) g_r2wh[i] = __float2half(r2w[i]);
    for (int i = t0; i < cI * cD * cH; i += gsz) g_quwh[i] = __float2half(quw[i]);
    for (int i = t0; i < cD * cD; i += gsz) g_outwh[i] = __float2half(outw[i]);
    for (int i = t0; i < cM * cD; i += gsz) g_xh[i] = __float2half(x[i]);
}

// ---------------- fp16 tensor-core GEMM, 3-stage, one sync per iter ---------
constexpr int GSH = 40;
constexpr int GS_A = 128 * GSH;
constexpr int GS_W = 64 * GSH;
constexpr int GS_STAGE = GS_A + GS_W;
constexpr int NSTAGE = 3;

// EPI: 0 f32 out | 2 gelu->half | 3 refined->half+acc | 4 gate | 5 final
template<int KDIM, int EPI, bool SPLITA>
__global__ __launch_bounds__(256) void mma_gemm_k(
    const __half* __restrict__ A, const __half* __restrict__ A2,
    const __half* __restrict__ W, const float* __restrict__ bias,
    float* __restrict__ C, __half* __restrict__ Ch, float* __restrict__ aux,
    const float* __restrict__ addsrc, int N, int flag)
{
    __shared__ __half dsm[NSTAGE * GS_STAGE];
    const int tid = threadIdx.x;
    const int warp = tid >> 5, lane = tid & 31;
    const int wm = warp >> 1, wn = warp & 1;
    const int gid = lane >> 2, tig = lane & 3;
    const int m0 = blockIdx.y * 128;
    const int n0 = blockIdx.x * 64;
    const int lda = SPLITA ? cD : KDIM;
    constexpr int NK = KDIM / 32;

    const int a_row = lane & 15;
    const int a_col = (lane >> 4) << 3;
    const int b_row = ((lane >> 4) << 3) + (lane & 7);
    const int b_col = ((lane >> 3) & 1) << 3;

    auto issue_stage = [&](int s, int k0) {
        __half* As = dsm + s * GS_STAGE;
        __half* Ws = As + GS_A;
        const __half* Ap = A;
        int kb = k0;
        if (SPLITA && k0 >= cD) { Ap = A2; kb = k0 - cD; }
#pragma unroll
        for (int r = 0; r < 2; r++) {
            int idx = tid + r * 256;
            int mm = idx >> 2, q = idx & 3;
            cp_async16(&As[mm * GSH + q * 8],
                       &Ap[(size_t)(m0 + mm) * lda + kb + q * 8]);
        }
        {
            int nn = tid >> 2, q = tid & 3;
            cp_async16(&Ws[nn * GSH + q * 8],
                       &W[(size_t)(n0 + nn) * KDIM + k0 + q * 8]);
        }
    };

    float acc[2][4][4];
#pragma unroll
    for (int i = 0; i < 2; i++)
#pragma unroll
        for (int j = 0; j < 4; j++)
#pragma unroll
            for (int r = 0; r < 4; r++) acc[i][j][r] = 0.f;

#pragma unroll
    for (int p = 0; p < NSTAGE - 1; p++) {
        if (p < NK) issue_stage(p, p * 32);
        asm volatile("cp.async.commit_group;\n");
    }

    for (int t = 0; t < NK; t++) {
        if (t == NK - 1) {
            asm volatile("cp.async.wait_group 0;\n");
        } else {
            asm volatile("cp.async.wait_group 1;\n");
        }
        __syncthreads();
        if (t + NSTAGE - 1 < NK) {
            issue_stage((t + NSTAGE - 1) % NSTAGE, (t + NSTAGE - 1) * 32);
            asm volatile("cp.async.commit_group;\n");
        }
        const __half* As = dsm + (t % NSTAGE) * GS_STAGE;
        const __half* Ws = As + GS_A;
#pragma unroll
        for (int ks = 0; ks < 2; ks++) {
            int kk = ks * 16;
            uint32_t a[2][4], b[4][2];
#pragma unroll
            for (int i = 0; i < 2; i++) {
                int mb = wm * 32 + i * 16;
                ldsm_x4(a[i][0], a[i][1], a[i][2], a[i][3],
                        &As[(mb + a_row) * GSH + kk + a_col]);
            }
#pragma unroll
            for (int jp = 0; jp < 2; jp++) {
                int nb = wn * 32 + jp * 16;
                ldsm_x4(b[jp * 2][0], b[jp * 2][1], b[jp * 2 + 1][0], b[jp * 2 + 1][1],
                        &Ws[(nb + b_row) * GSH + kk + b_col]);
            }
#pragma unroll
            for (int i = 0; i < 2; i++)
#pragma unroll
                for (int j = 0; j < 4; j++) mma_f16(acc[i][j], a[i], b[j]);
        }
    }

#pragma unroll
    for (int i = 0; i < 2; i++)
#pragma unroll
        for (int j = 0; j < 4; j++)
#pragma unroll
            for (int r = 0; r < 4; r++) {
                int m = m0 + wm * 32 + i * 16 + gid + ((r >= 2) ? 8 : 0);
                int n = n0 + wn * 32 + j * 8 + tig * 2 + (r & 1);
                float v = acc[i][j][r] + bias[n];
                size_t o = (size_t)m * N + n;
                if constexpr (EPI == 0) {
                    C[o] = v;
                } else if constexpr (EPI == 2) {
                    v = 0.5f * v * (1.f + erff(v * 0.7071067811865476f));
                    Ch[o] = __float2half(v);
                } else if constexpr (EPI == 3) {
                    Ch[o] = __float2half(v);
                    aux[o] = flag ? v : (aux[o] + v);
                } else if constexpr (EPI == 4) {
                    float q = addsrc[o] + tanhf(v);
                    C[o] = q;
                    Ch[o] = __float2half(q);
                } else if constexpr (EPI == 5) {
                    C[o] = addsrc[o] + v;
                }
            }
}

// ---------------- fp32 phase GEMM, BM=32 for full-chip occupancy -----------
__global__ __launch_bounds__(256) void phase_gemm_k(
    const float* __restrict__ A, const float* __restrict__ W,
    const float* __restrict__ bias, float* __restrict__ C)
{
    __shared__ float As[32][17];
    __shared__ float Ws[64][17];
    const int tid = threadIdx.x;
    const int tx = tid & 15, ty = tid >> 4;
    const int m0 = blockIdx.x * 32;
    constexpr int KDIM = 256;

    float acc[2][4];
#pragma unroll
    for (int i = 0; i < 2; i++)
#pragma unroll
        for (int j = 0; j < 4; j++) acc[i][j] = 0.f;

    for (int k0 = 0; k0 < KDIM; k0 += 16) {
        if (tid < 128) {
            int mm = tid >> 2, q = tid & 3;
            float4 a4 = *reinterpret_cast<const float4*>(
                &A[(size_t)(m0 + mm) * KDIM + k0 + q * 4]);
            As[mm][q * 4 + 0] = a4.x; As[mm][q * 4 + 1] = a4.y;
            As[mm][q * 4 + 2] = a4.z; As[mm][q * 4 + 3] = a4.w;
        }
        {
            int nn = tid >> 2, q = tid & 3;
            float4 w4 = *reinterpret_cast<const float4*>(
                &W[(size_t)nn * KDIM + k0 + q * 4]);
            Ws[nn][q * 4 + 0] = w4.x; Ws[nn][q * 4 + 1] = w4.y;
            Ws[nn][q * 4 + 2] = w4.z; Ws[nn][q * 4 + 3] = w4.w;
        }
        __syncthreads();
#pragma unroll
        for (int kk = 0; kk < 16; kk++) {
            float ra[2], rb[4];
#pragma unroll
            for (int i = 0; i < 2; i++) ra[i] = As[ty * 2 + i][kk];
#pragma unroll
            for (int j = 0; j < 4; j++) rb[j] = Ws[tx * 4 + j][kk];
#pragma unroll
            for (int i = 0; i < 2; i++)
#pragma unroll
                for (int j = 0; j < 4; j++) acc[i][j] = fmaf(ra[i], rb[j], acc[i][j]);
        }
        __syncthreads();
    }

#pragma unroll
    for (int i = 0; i < 2; i++) {
        int m = m0 + ty * 2 + i;
#pragma unroll
        for (int j = 0; j < 4; j++) {
            int n = tx * 4 + j;
            float v = acc[i][j] + bias[n];
            float t = tanhf(v) * PI_F;
            float sn, cs;
            sincosf(t, &sn, &cs);
            int bb = m / cL, l = m % cL;
            int kbank = n >> 4, p = n & 15;
            size_t base = ((size_t)(bb * cK + kbank) * cL + l) * cF;
            C[base + p] = cs;
            C[base + cP + p] = sn;
        }
    }
}

// ------------- chunk states via tf32 mma: state = Mf^T @ V -----------------
__global__ __launch_bounds__(256) void chunk_mma_k(
    const float* __restrict__ mfeat, const float* __restrict__ V,
    float* __restrict__ state)
{
    constexpr int SMH = 40;
    constexpr int SVW = 136;
    __shared__ uint32_t sMf[cCH * SMH];
    __shared__ uint32_t sV[cCH * SVW];
    const int ci = blockIdx.x, bk = blockIdx.y;
    const int bb = bk >> 2, kk2 = bk & 3;
    const int tid = threadIdx.x;
    const int warp = tid >> 5, lane = tid & 31;
    const int gid = lane >> 2, tig = lane & 3;

    const size_t featBase = ((size_t)(bb * cK + kk2) * cL + (size_t)ci * cCH) * cF;
#pragma unroll
    for (int r = 0; r < 2; r++) {
        int idx4 = tid + r * 256;
        int row = idx4 >> 3, q = idx4 & 7;
        float4 a4 = *reinterpret_cast<const float4*>(&mfeat[featBase + (size_t)row * cF + q * 4]);
        uint32_t* s = &sMf[row * SMH + q * 4];
        s[0] = f2tf(a4.x); s[1] = f2tf(a4.y); s[2] = f2tf(a4.z); s[3] = f2tf(a4.w);
    }
    const size_t vBase = ((size_t)(bb * cL) + (size_t)ci * cCH) * cD;
    const size_t stBase = (((size_t)(bb * cK + kk2) * cNC + ci) * cF) * cD;

    for (int dh = 0; dh < 2; dh++) {
        if (dh) __syncthreads();
#pragma unroll
        for (int r = 0; r < 8; r++) {
            int idx4 = tid + r * 256;
            int row = idx4 >> 5, q = idx4 & 31;
            float4 v4 = *reinterpret_cast<const float4*>(&V[vBase + (size_t)row * cD + dh * 128 + q * 4]);
            uint32_t* s = &sV[row * SVW + q * 4];
            s[0] = f2tf(v4.x); s[1] = f2tf(v4.y); s[2] = f2tf(v4.z); s[3] = f2tf(v4.w);
        }
        __syncthreads();

        float acc[2][2][4];
#pragma unroll
        for (int i = 0; i < 2; i++)
#pragma unroll
            for (int j = 0; j < 2; j++)
#pragma unroll
                for (int r = 0; r < 4; r++) acc[i][j][r] = 0.f;

#pragma unroll
        for (int ks = 0; ks < 8; ks++) {
            int kk = ks * 8;
            uint32_t a[2][4], b[2][2];
#pragma unroll
            for (int i = 0; i < 2; i++) {
                int mb = i * 16;
                a[i][0] = sMf[(kk + tig) * SMH + mb + gid];
                a[i][1] = sMf[(kk + tig) * SMH + mb + gid + 8];
                a[i][2] = sMf[(kk + tig + 4) * SMH + mb + gid];
                a[i][3] = sMf[(kk + tig + 4) * SMH + mb + gid + 8];
            }
#pragma unroll
            for (int j = 0; j < 2; j++) {
                int nb = warp * 16 + j * 8;
                b[j][0] = sV[(kk + tig) * SVW + nb + gid];
                b[j][1] = sV[(kk + tig + 4) * SVW + nb + gid];
            }
#pragma unroll
            for (int i = 0; i < 2; i++)
#pragma unroll
                for (int j = 0; j < 2; j++) mma_tf32(acc[i][j], a[i], b[j]);
        }

#pragma unroll
        for (int i = 0; i < 2; i++)
#pragma unroll
            for (int j = 0; j < 2; j++)
#pragma unroll
                for (int r = 0; r < 4; r++) {
                    int f = i * 16 + gid + ((r >= 2) ? 8 : 0);
                    int d = dh * 128 + warp * 16 + j * 8 + tig * 2 + (r & 1);
                    state[stBase + (size_t)f * cD + d] = acc[i][j][r];
                }
    }
}

// ------------- exclusive prefix scan, MLP-batched loads --------------------
__global__ __launch_bounds__(256) void scan_k(float* __restrict__ state)
{
    int u = blockIdx.x * 256 + threadIdx.x;
    if (u >= cB * cK * cF * cD) return;
    int fd = u & (cF * cD - 1);
    int bk = u >> 13;
    float* base = state + (size_t)bk * cNC * cF * cD + fd;
    float v[cNC];
#pragma unroll
    for (int ci = 0; ci < cNC; ci++)
        v[ci] = base[(size_t)ci * cF * cD];
    float run = 0.f;
#pragma unroll
    for (int ci = 0; ci < cNC; ci++) {
        base[(size_t)ci * cF * cD] = run;
        run += v[ci];
    }
}

// ------------- retrieval via tf32 mma, d-split across blockIdx.z -----------
// R = Qf@S + tril(Qf@Mf^T)@V. Each block handles 2 of the 4 d-quarters.
__global__ __launch_bounds__(256) void retrieve_mma_k(
    const float* __restrict__ qfeat, const float* __restrict__ mfeat,
    const float* __restrict__ state, const float* __restrict__ V,
    float* __restrict__ comb)
{
    constexpr int SQ = 36;
    constexpr int SAs = 68;
    constexpr int SB = 72;
    __shared__ uint32_t sQ[64 * SQ];
    __shared__ uint32_t sA[64 * SAs];
    __shared__ uint32_t sB[64 * SB];

    const int ci = blockIdx.x;
    const int bk = blockIdx.y;
    const int zh = blockIdx.z;          // 0 or 1: which pair of d-quarters
    const int bb = bk >> 2, kb = bk & 3;
    const int tid = threadIdx.x;
    const int warp = tid >> 5, lane = tid & 31;
    const int wm2 = warp >> 2, wn4 = warp & 3;
    const int gid = lane >> 2, tig = lane & 3;

    const size_t featBase = ((size_t)(bb * cK + kb) * cL + (size_t)ci * cCH) * cF;
#pragma unroll
    for (int r = 0; r < 2; r++) {
        int idx4 = tid + r * 256;
        int row = idx4 >> 3, q = idx4 & 7;
        float4 a4 = *reinterpret_cast<const float4*>(&qfeat[featBase + (size_t)row * cF + q * 4]);
        uint32_t* s = &sQ[row * SQ + q * 4];
        s[0] = f2tf(a4.x); s[1] = f2tf(a4.y); s[2] = f2tf(a4.z); s[3] = f2tf(a4.w);
        float4 m4 = *reinterpret_cast<const float4*>(&mfeat[featBase + (size_t)row * cF + q * 4]);
        uint32_t* t = &sB[row * SQ + q * 4];
        t[0] = f2tf(m4.x); t[1] = f2tf(m4.y); t[2] = f2tf(m4.z); t[3] = f2tf(m4.w);
    }
    __syncthreads();

    // A = tril(Qf @ Mf^T)  (recomputed per z-block; deterministic)
    {
        float accA[2][2][4];
#pragma unroll
        for (int i = 0; i < 2; i++)
#pragma unroll
            for (int j = 0; j < 2; j++)
#pragma unroll
                for (int r = 0; r < 4; r++) accA[i][j][r] = 0.f;
#pragma unroll
        for (int ks = 0; ks < 4; ks++) {
            int kk = ks * 8;
            uint32_t a[2][4], b[2][2];
#pragma unroll
            for (int i = 0; i < 2; i++) {
                int mb = wm2 * 32 + i * 16;
                a[i][0] = sQ[(mb + gid) * SQ + kk + tig];
                a[i][1] = sQ[(mb + gid + 8) * SQ + kk + tig];
                a[i][2] = sQ[(mb + gid) * SQ + kk + tig + 4];
                a[i][3] = sQ[(mb + gid + 8) * SQ + kk + tig + 4];
            }
#pragma unroll
            for (int j = 0; j < 2; j++) {
                int nb = wn4 * 16 + j * 8;
                b[j][0] = sB[(nb + gid) * SQ + kk + tig];
                b[j][1] = sB[(nb + gid) * SQ + kk + tig + 4];
            }
#pragma unroll
            for (int i = 0; i < 2; i++)
#pragma unroll
                for (int j = 0; j < 2; j++) mma_tf32(accA[i][j], a[i], b[j]);
        }
        __syncthreads();
#pragma unroll
        for (int i = 0; i < 2; i++)
#pragma unroll
            for (int j = 0; j < 2; j++)
#pragma unroll
                for (int r = 0; r < 4; r++) {
                    int m = wm2 * 32 + i * 16 + gid + ((r >= 2) ? 8 : 0);
                    int n = wn4 * 16 + j * 8 + tig * 2 + (r & 1);
                    float v = (n <= m) ? accA[i][j][r] : 0.f;
                    sA[m * SAs + n] = f2tf(v);
                }
    }
    __syncthreads();

    const size_t stBase = (((size_t)(bb * cK + kb) * cNC + ci) * cF) * cD;
    const size_t vBase = ((size_t)(bb * cL) + (size_t)ci * cCH) * cD;

    for (int dq = 0; dq < 2; dq++) {
        const int dh = zh * 2 + dq;
        __syncthreads();
#pragma unroll
        for (int r = 0; r < 2; r++) {
            int idx4 = tid + r * 256;
            int f = idx4 >> 4, q = idx4 & 15;
            float4 s4 = *reinterpret_cast<const float4*>(&state[stBase + (size_t)f * cD + dh * 64 + q * 4]);
            uint32_t* s = &sB[f * SB + q * 4];
            s[0] = f2tf(s4.x); s[1] = f2tf(s4.y); s[2] = f2tf(s4.z); s[3] = f2tf(s4.w);
        }
        __syncthreads();

        float accO[2][2][4];
#pragma unroll
        for (int i = 0; i < 2; i++)
#pragma unroll
            for (int j = 0; j < 2; j++)
#pragma unroll
                for (int r = 0; r < 4; r++) accO[i][j][r] = 0.f;

#pragma unroll
        for (int ks = 0; ks < 4; ks++) {
            int kk = ks * 8;
            uint32_t a[2][4], b[2][2];
#pragma unroll
            for (int i = 0; i < 2; i++) {
                int mb = wm2 * 32 + i * 16;
                a[i][0] = sQ[(mb + gid) * SQ + kk + tig];
                a[i][1] = sQ[(mb + gid + 8) * SQ + kk + tig];
                a[i][2] = sQ[(mb + gid) * SQ + kk + tig + 4];
                a[i][3] = sQ[(mb + gid + 8) * SQ + kk + tig + 4];
            }
#pragma unroll
            for (int j = 0; j < 2; j++) {
                int nb = wn4 * 16 + j * 8;
                b[j][0] = sB[(kk + tig) * SB + nb + gid];
                b[j][1] = sB[(kk + tig + 4) * SB + nb + gid];
            }
#pragma unroll
            for (int i = 0; i < 2; i++)
#pragma unroll
                for (int j = 0; j < 2; j++) mma_tf32(accO[i][j], a[i], b[j]);
        }
        __syncthreads();
#pragma unroll
        for (int r = 0; r < 4; r++) {
            int idx4 = tid + r * 256;
            int row = idx4 >> 4, q = idx4 & 15;
            float4 v4 = *reinterpret_cast<const float4*>(&V[vBase + (size_t)row * cD + dh * 64 + q * 4]);
            uint32_t* s = &sB[row * SB + q * 4];
            s[0] = f2tf(v4.x); s[1] = f2tf(v4.y); s[2] = f2tf(v4.z); s[3] = f2tf(v4.w);
        }
        __syncthreads();

#pragma unroll
        for (int ks = 0; ks < 8; ks++) {
            int kk = ks * 8;
            uint32_t a[2][4], b[2][2];
#pragma unroll
            for (int i = 0; i < 2; i++) {
                int mb = wm2 * 32 + i * 16;
                a[i][0] = sA[(mb + gid) * SAs + kk + tig];
                a[i][1] = sA[(mb + gid + 8) * SAs + kk + tig];
                a[i][2] = sA[(mb + gid) * SAs + kk + tig + 4];
                a[i][3] = sA[(mb + gid + 8) * SAs + kk + tig + 4];
            }
#pragma unroll
            for (int j = 0; j < 2; j++) {
                int nb = wn4 * 16 + j * 8;
                b[j][0] = sB[(kk + tig) * SB + nb + gid];
                b[j][1] = sB[(kk + tig + 4) * SB + nb + gid];
            }
#pragma unroll
            for (int i = 0; i < 2; i++)
#pragma unroll
                for (int j = 0; j < 2; j++) mma_tf32(accO[i][j], a[i], b[j]);
        }

#pragma unroll
        for (int i = 0; i < 2; i++)
#pragma unroll
            for (int j = 0; j < 2; j++)
#pragma unroll
                for (int r = 0; r < 4; r++) {
                    int ml = wm2 * 32 + i * 16 + gid + ((r >= 2) ? 8 : 0);
                    int nl = wn4 * 16 + j * 8 + tig * 2 + (r & 1);
                    int l = ci * cCH + ml;
                    float sc = rsqrtf(16.f * (float)(l + 1));
                    comb[((size_t)(bb * cL + l)) * cKD + (size_t)kb * cD + dh * 64 + nl] =
                        accO[i][j][r] * sc;
                }
    }
}

// ------------- row LayerNorm (fp32 in, half out), vectorized ----------------
template<int NDIM>
__global__ __launch_bounds__(256) void ln_h_k(
    const float* __restrict__ in, const float* __restrict__ w,
    const float* __restrict__ bsh, __half* __restrict__ out)
{
    const int row = blockIdx.x;
    const float* xp = in + (size_t)row * NDIM;
    constexpr int R = NDIM / 256;
    float vals[R];
    float s = 0.f, s2 = 0.f;
    if constexpr (R == 4) {
        float4 v4 = reinterpret_cast<const float4*>(xp)[threadIdx.x];
        vals[0] = v4.x; vals[1] = v4.y; vals[2] = v4.z; vals[3] = v4.w;
#pragma unroll
        for (int r = 0; r < 4; r++) { s += vals[r]; s2 += vals[r] * vals[r]; }
    } else {
#pragma unroll
        for (int r = 0; r < R; r++) {
            float v = xp[threadIdx.x + r * 256];
            vals[r] = v; s += v; s2 += v * v;
        }
    }
#pragma unroll
    for (int o = 16; o > 0; o >>= 1) {
        s += __shfl_xor_sync(0xffffffffu, s, o);
        s2 += __shfl_xor_sync(0xffffffffu, s2, o);
    }
    __shared__ float rs[8], rs2[8], sm[2];
    int wid = threadIdx.x >> 5, lane = threadIdx.x & 31;
    if (lane == 0) { rs[wid] = s; rs2[wid] = s2; }
    __syncthreads();
    if (threadIdx.x == 0) {
        float a = 0.f, c = 0.f;
        for (int i = 0; i < 8; i++) { a += rs[i]; c += rs2[i]; }
        float mean = a / NDIM;
        float var = c / NDIM - mean * mean;
        sm[0] = mean;
        sm[1] = rsqrtf(fmaxf(var, 0.f) + 1e-5f);
    }
    __syncthreads();
    float mean = sm[0], inv = sm[1];
    __half* op = out + (size_t)row * NDIM;
    if constexpr (R == 4) {
        float4 w4 = reinterpret_cast<const float4*>(w)[threadIdx.x];
        float4 b4 = reinterpret_cast<const float4*>(bsh)[threadIdx.x];
        __half2 h0 = __floats2half2_rn((vals[0] - mean) * inv * w4.x + b4.x,
                                       (vals[1] - mean) * inv * w4.y + b4.y);
        __half2 h1 = __floats2half2_rn((vals[2] - mean) * inv * w4.z + b4.z,
                                       (vals[3] - mean) * inv * w4.w + b4.w);
        uint32_t lo, hi;
        memcpy(&lo, &h0, 4);
        memcpy(&hi, &h1, 4);
        reinterpret_cast<uint2*>(op)[threadIdx.x] = make_uint2(lo, hi);
    } else {
#pragma unroll
        for (int r = 0; r < R; r++) {
            int i = threadIdx.x + r * 256;
            op[i] = __float2half((vals[r] - mean) * inv * w[i] + bsh[i]);
        }
    }
}

// ------------- host orchestration ------------------------------------------
extern "C" void kernel_launch(void* const* d_in, const int* in_sizes, int n_in,
                              void* d_out, int out_size)
{
    const float* x       = (const float*)d_in[0];
    const float* phase_w = (const float*)d_in[1];
    const float* phase_b = (const float*)d_in[2];
    const float* val_w   = (const float*)d_in[3];
    const float* val_b   = (const float*)d_in[4];
    const float* rlnw    = (const float*)d_in[5];
    const float* rlnb    = (const float*)d_in[6];
    const float* r1w     = (const float*)d_in[7];
    const float* r1b     = (const float*)d_in[8];
    const float* r2w     = (const float*)d_in[9];
    const float* r2b     = (const float*)d_in[10];
    const float* quw     = (const float*)d_in[11];
    const float* qub     = (const float*)d_in[12];
    const float* olnw    = (const float*)d_in[13];
    const float* olnb    = (const float*)d_in[14];
    const float* outw    = (const float*)d_in[15];
    const float* outb    = (const float*)d_in[16];
    float* out = (float*)d_out;

    float *V, *Mf, *Qf, *St, *Cb, *Ac, *Q0, *Q1;
    cudaGetSymbolAddress((void**)&V,  g_V);
    cudaGetSymbolAddress((void**)&Mf, g_Mfeat);
    cudaGetSymbolAddress((void**)&Qf, g_Qfeat);
    cudaGetSymbolAddress((void**)&St, g_state);
    cudaGetSymbolAddress((void**)&Cb, g_comb);
    cudaGetSymbolAddress((void**)&Ac, g_acc);
    cudaGetSymbolAddress((void**)&Q0, g_q0);
    cudaGetSymbolAddress((void**)&Q1, g_q1);
    __half *Xh, *Clh, *Hhh, *Rfh, *Q0h, *Q1h, *Alh;
    __half *ValWh, *R1Wh, *R2Wh, *QuWh, *OutWh;
    cudaGetSymbolAddress((void**)&Xh,  g_xh);
    cudaGetSymbolAddress((void**)&Clh, g_Clh);
    cudaGetSymbolAddress((void**)&Hhh, g_Hhh);
    cudaGetSymbolAddress((void**)&Rfh, g_Rfh);
    cudaGetSymbolAddress((void**)&Q0h, g_q0h);
    cudaGetSymbolAddress((void**)&Q1h, g_q1h);
    cudaGetSymbolAddress((void**)&Alh, g_Alh);
    cudaGetSymbolAddress((void**)&ValWh, g_valwh);
    cudaGetSymbolAddress((void**)&R1Wh, g_r1wh);
    cudaGetSymbolAddress((void**)&R2Wh, g_r2wh);
    cudaGetSymbolAddress((void**)&QuWh, g_quwh);
    cudaGetSymbolAddress((void**)&OutWh, g_outwh);

    // convert weights + x to half
    cvt_h_k<<<512, 256>>>(val_w, r1w, r2w, quw, outw, x);

    // values GEMM (fp16 mma) -> fp32 V
    mma_gemm_k<256, 0, false><<<dim3(cD / 64, cM / 128), 256>>>(
        Xh, nullptr, ValWh, val_b, V, nullptr, nullptr, nullptr, cD, 0);
    // memory-side phase features (fp32)
    phase_gemm_k<<<cM / 32, 256>>>(x, phase_w, phase_b, Mf);
    // chunk states via tf32 mma + scan
    chunk_mma_k<<<dim3(cNC, cB * cK), 256>>>(Mf, V, St);
    scan_k<<<256, 256>>>(St);

    const float* qin = x;
    const __half* qinh = Xh;
    for (int i = 0; i < cI; i++) {
        float* qout = (i & 1) ? Q1 : Q0;
        __half* qouth = (i & 1) ? Q1h : Q0h;
        phase_gemm_k<<<cM / 32, 256>>>(qin, phase_w, phase_b, Qf);
        retrieve_mma_k<<<dim3(cNC, cB * cK, 2), 256>>>(Qf, Mf, St, V, Cb);
        ln_h_k<1024><<<cM, 256>>>(Cb, rlnw + (size_t)i * cKD, rlnb + (size_t)i * cKD, Clh);
        mma_gemm_k<1024, 2, false><<<dim3(cH / 64, cM / 128), 256>>>(
            Clh, nullptr, R1Wh + (size_t)i * cH * cKD, r1b + (size_t)i * cH,
            nullptr, Hhh, nullptr, nullptr, cH, 0);
        mma_gemm_k<512, 3, false><<<dim3(cD / 64, cM / 128), 256>>>(
            Hhh, nullptr, R2Wh + (size_t)i * cD * cH, r2b + (size_t)i * cD,
            nullptr, Rfh, Ac, nullptr, cD, (i == 0) ? 1 : 0);
        mma_gemm_k<512, 4, true><<<dim3(cD / 64, cM / 128), 256>>>(
            qinh, Rfh, QuWh + (size_t)i * cD * cH, qub + (size_t)i * cD,
            qout, qouth, nullptr, qin, cD, 0);
        qin = qout;
        qinh = qouth;
    }

    ln_h_k<256><<<cM, 256>>>(Ac, olnw, olnb, Alh);
    mma_gemm_k<256, 5, false><<<dim3(cD / 64, cM / 128), 256>>>(
        Alh, nullptr, OutWh, outb, out, nullptr, nullptr, x, cD, 0);
}

// round 17
// speedup vs baseline: 1.0185x; 1.0185x over previous
#include <cuda_runtime.h>
#include <cuda_fp16.h>
#include <cstdint>
#include <cstddef>
#include <math.h>

// Problem constants (fixed by setup_inputs)
constexpr int cB = 2, cL = 2048, cD = 256, cP = 16, cK = 4, cI = 3;
constexpr int cF = 32;
constexpr int cKD = 1024;
constexpr int cH = 512;
constexpr int cCH = 64;
constexpr int cNC = cL / cCH;
constexpr int cM = cB * cL;
#define PI_F 3.14159265358979323846f

// ---------------- scratch ---------------------------------------------------
__device__ float g_V[cM * cD];
__device__ float g_Mfeat[cB * cK * cL * cF];
__device__ float g_Qfeat[cB * cK * cL * cF];
__device__ float g_state[cB * cK * cNC * cF * cD];
__device__ float g_comb[cM * cKD];
__device__ float g_acc[cM * cD];
__device__ float g_q0[cM * cD];
__device__ float g_q1[cM * cD];
// half activation buffers
__device__ __half g_xh[cM * cD];
__device__ __half g_Clh[cM * cKD];
__device__ __half g_Hhh[cM * cH];
__device__ __half g_Rfh[cM * cD];
__device__ __half g_q0h[cM * cD];
__device__ __half g_q1h[cM * cD];
__device__ __half g_Alh[cM * cD];
// half weights
__device__ __half g_valwh[cD * cD];
__device__ __half g_r1wh[cI * cH * cKD];
__device__ __half g_r2wh[cI * cD * cH];
__device__ __half g_quwh[cI * cD * cH];
__device__ __half g_outwh[cD * cD];

// ---------------- helpers ---------------------------------------------------
__device__ __forceinline__ uint32_t f2tf(float x) {
    uint32_t r;
    asm("cvt.rna.tf32.f32 %0, %1;" : "=r"(r) : "f"(x));
    return r;
}
__device__ __forceinline__ void mma_tf32(float* c, const uint32_t* a, const uint32_t* b) {
    asm volatile(
        "mma.sync.aligned.m16n8k8.row.col.f32.tf32.tf32.f32 "
        "{%0,%1,%2,%3}, {%4,%5,%6,%7}, {%8,%9}, {%0,%1,%2,%3};\n"
        : "+f"(c[0]), "+f"(c[1]), "+f"(c[2]), "+f"(c[3])
        : "r"(a[0]), "r"(a[1]), "r"(a[2]), "r"(a[3]), "r"(b[0]), "r"(b[1]));
}
__device__ __forceinline__ void mma_f16(float* c, const uint32_t* a, const uint32_t* b) {
    asm volatile(
        "mma.sync.aligned.m16n8k16.row.col.f32.f16.f16.f32 "
        "{%0,%1,%2,%3}, {%4,%5,%6,%7}, {%8,%9}, {%0,%1,%2,%3};\n"
        : "+f"(c[0]), "+f"(c[1]), "+f"(c[2]), "+f"(c[3])
        : "r"(a[0]), "r"(a[1]), "r"(a[2]), "r"(a[3]), "r"(b[0]), "r"(b[1]));
}
__device__ __forceinline__ void cp_async16(void* smem_dst, const void* gsrc) {
    uint32_t s = (uint32_t)__cvta_generic_to_shared(smem_dst);
    asm volatile("cp.async.cg.shared.global [%0], [%1], 16;\n" :: "r"(s), "l"(gsrc));
}
__device__ __forceinline__ void ldsm_x4(uint32_t& r0, uint32_t& r1, uint32_t& r2,
                                        uint32_t& r3, const void* p) {
    uint32_t addr = (uint32_t)__cvta_generic_to_shared(p);
    asm volatile("ldmatrix.sync.aligned.m8n8.x4.shared.b16 {%0,%1,%2,%3}, [%4];\n"
        : "=r"(r0), "=r"(r1), "=r"(r2), "=r"(r3) : "r"(addr));
}
__device__ __forceinline__ void cvt4(const float* __restrict__ src,
                                     __half* __restrict__ dst, int i4) {
    float4 v = reinterpret_cast<const float4*>(src)[i4];
    __half2 h0 = __floats2half2_rn(v.x, v.y);
    __half2 h1 = __floats2half2_rn(v.z, v.w);
    uint32_t lo, hi;
    memcpy(&lo, &h0, 4);
    memcpy(&hi, &h1, 4);
    reinterpret_cast<uint2*>(dst)[i4] = make_uint2(lo, hi);
}

// ---------------- weight / x fp32->fp16 conversion, vectorized --------------
__global__ __launch_bounds__(256) void cvt_h_k(
    const float* __restrict__ val_w, const float* __restrict__ r1w,
    const float* __restrict__ r2w, const float* __restrict__ quw,
    const float* __restrict__ outw, const float* __restrict__ x)
{
    int gsz = gridDim.x * blockDim.x;
    int t0 = blockIdx.x * blockDim.x + threadIdx.x;
    for (int i = t0; i < (cD * cD) / 4; i += gsz) cvt4(val_w, g_valwh, i);
    for (int i = t0; i < (cI * cH * cKD) / 4; i += gsz) cvt4(r1w, g_r1wh, i);
    for (int i = t0; i < (cI * cD * cH) / 4; i += gsz) cvt4(r2w, g_r2wh, i);
    for (int i = t0; i < (cI * cD * cH) / 4; i += gsz) cvt4(quw, g_quwh, i);
    for (int i = t0; i < (cD * cD) / 4; i += gsz) cvt4(outw, g_outwh, i);
    for (int i = t0; i < (cM * cD) / 4; i += gsz) cvt4(x, g_xh, i);
}

// ---------------- fp16 tensor-core GEMM, 3-stage, one sync per iter ---------
constexpr int GSH = 40;
constexpr int GS_A = 128 * GSH;
constexpr int GS_W = 64 * GSH;
constexpr int GS_STAGE = GS_A + GS_W;
constexpr int NSTAGE = 3;

// EPI: 0 f32 out | 2 gelu->half | 3 refined->half+acc | 4 gate | 5 final
template<int KDIM, int EPI, bool SPLITA>
__global__ __launch_bounds__(256) void mma_gemm_k(
    const __half* __restrict__ A, const __half* __restrict__ A2,
    const __half* __restrict__ W, const float* __restrict__ bias,
    float* __restrict__ C, __half* __restrict__ Ch, float* __restrict__ aux,
    const float* __restrict__ addsrc, int N, int flag)
{
    __shared__ __half dsm[NSTAGE * GS_STAGE];
    const int tid = threadIdx.x;
    const int warp = tid >> 5, lane = tid & 31;
    const int wm = warp >> 1, wn = warp & 1;
    const int gid = lane >> 2, tig = lane & 3;
    const int m0 = blockIdx.y * 128;
    const int n0 = blockIdx.x * 64;
    const int lda = SPLITA ? cD : KDIM;
    constexpr int NK = KDIM / 32;

    const int a_row = lane & 15;
    const int a_col = (lane >> 4) << 3;
    const int b_row = ((lane >> 4) << 3) + (lane & 7);
    const int b_col = ((lane >> 3) & 1) << 3;

    auto issue_stage = [&](int s, int k0) {
        __half* As = dsm + s * GS_STAGE;
        __half* Ws = As + GS_A;
        const __half* Ap = A;
        int kb = k0;
        if (SPLITA && k0 >= cD) { Ap = A2; kb = k0 - cD; }
#pragma unroll
        for (int r = 0; r < 2; r++) {
            int idx = tid + r * 256;
            int mm = idx >> 2, q = idx & 3;
            cp_async16(&As[mm * GSH + q * 8],
                       &Ap[(size_t)(m0 + mm) * lda + kb + q * 8]);
        }
        {
            int nn = tid >> 2, q = tid & 3;
            cp_async16(&Ws[nn * GSH + q * 8],
                       &W[(size_t)(n0 + nn) * KDIM + k0 + q * 8]);
        }
    };

    float acc[2][4][4];
#pragma unroll
    for (int i = 0; i < 2; i++)
#pragma unroll
        for (int j = 0; j < 4; j++)
#pragma unroll
            for (int r = 0; r < 4; r++) acc[i][j][r] = 0.f;

#pragma unroll
    for (int p = 0; p < NSTAGE - 1; p++) {
        if (p < NK) issue_stage(p, p * 32);
        asm volatile("cp.async.commit_group;\n");
    }

    for (int t = 0; t < NK; t++) {
        if (t == NK - 1) {
            asm volatile("cp.async.wait_group 0;\n");
        } else {
            asm volatile("cp.async.wait_group 1;\n");
        }
        __syncthreads();
        if (t + NSTAGE - 1 < NK) {
            issue_stage((t + NSTAGE - 1) % NSTAGE, (t + NSTAGE - 1) * 32);
            asm volatile("cp.async.commit_group;\n");
        }
        const __half* As = dsm + (t % NSTAGE) * GS_STAGE;
        const __half* Ws = As + GS_A;
#pragma unroll
        for (int ks = 0; ks < 2; ks++) {
            int kk = ks * 16;
            uint32_t a[2][4], b[4][2];
#pragma unroll
            for (int i = 0; i < 2; i++) {
                int mb = wm * 32 + i * 16;
                ldsm_x4(a[i][0], a[i][1], a[i][2], a[i][3],
                        &As[(mb + a_row) * GSH + kk + a_col]);
            }
#pragma unroll
            for (int jp = 0; jp < 2; jp++) {
                int nb = wn * 32 + jp * 16;
                ldsm_x4(b[jp * 2][0], b[jp * 2][1], b[jp * 2 + 1][0], b[jp * 2 + 1][1],
                        &Ws[(nb + b_row) * GSH + kk + b_col]);
            }
#pragma unroll
            for (int i = 0; i < 2; i++)
#pragma unroll
                for (int j = 0; j < 4; j++) mma_f16(acc[i][j], a[i], b[j]);
        }
    }

#pragma unroll
    for (int i = 0; i < 2; i++)
#pragma unroll
        for (int j = 0; j < 4; j++)
#pragma unroll
            for (int r = 0; r < 4; r++) {
                int m = m0 + wm * 32 + i * 16 + gid + ((r >= 2) ? 8 : 0);
                int n = n0 + wn * 32 + j * 8 + tig * 2 + (r & 1);
                float v = acc[i][j][r] + bias[n];
                size_t o = (size_t)m * N + n;
                if constexpr (EPI == 0) {
                    C[o] = v;
                } else if constexpr (EPI == 2) {
                    v = 0.5f * v * (1.f + erff(v * 0.7071067811865476f));
                    Ch[o] = __float2half(v);
                } else if constexpr (EPI == 3) {
                    Ch[o] = __float2half(v);
                    aux[o] = flag ? v : (aux[o] + v);
                } else if constexpr (EPI == 4) {
                    float q = addsrc[o] + tanhf(v);
                    C[o] = q;
                    Ch[o] = __float2half(q);
                } else if constexpr (EPI == 5) {
                    C[o] = addsrc[o] + v;
                }
            }
}

// ---------------- fp32 phase GEMM, BM=32 for full-chip occupancy -----------
__global__ __launch_bounds__(256) void phase_gemm_k(
    const float* __restrict__ A, const float* __restrict__ W,
    const float* __restrict__ bias, float* __restrict__ C)
{
    __shared__ float As[32][17];
    __shared__ float Ws[64][17];
    const int tid = threadIdx.x;
    const int tx = tid & 15, ty = tid >> 4;
    const int m0 = blockIdx.x * 32;
    constexpr int KDIM = 256;

    float acc[2][4];
#pragma unroll
    for (int i = 0; i < 2; i++)
#pragma unroll
        for (int j = 0; j < 4; j++) acc[i][j] = 0.f;

    for (int k0 = 0; k0 < KDIM; k0 += 16) {
        if (tid < 128) {
            int mm = tid >> 2, q = tid & 3;
            float4 a4 = *reinterpret_cast<const float4*>(
                &A[(size_t)(m0 + mm) * KDIM + k0 + q * 4]);
            As[mm][q * 4 + 0] = a4.x; As[mm][q * 4 + 1] = a4.y;
            As[mm][q * 4 + 2] = a4.z; As[mm][q * 4 + 3] = a4.w;
        }
        {
            int nn = tid >> 2, q = tid & 3;
            float4 w4 = *reinterpret_cast<const float4*>(
                &W[(size_t)nn * KDIM + k0 + q * 4]);
            Ws[nn][q * 4 + 0] = w4.x; Ws[nn][q * 4 + 1] = w4.y;
            Ws[nn][q * 4 + 2] = w4.z; Ws[nn][q * 4 + 3] = w4.w;
        }
        __syncthreads();
#pragma unroll
        for (int kk = 0; kk < 16; kk++) {
            float ra[2], rb[4];
#pragma unroll
            for (int i = 0; i < 2; i++) ra[i] = As[ty * 2 + i][kk];
#pragma unroll
            for (int j = 0; j < 4; j++) rb[j] = Ws[tx * 4 + j][kk];
#pragma unroll
            for (int i = 0; i < 2; i++)
#pragma unroll
                for (int j = 0; j < 4; j++) acc[i][j] = fmaf(ra[i], rb[j], acc[i][j]);
        }
        __syncthreads();
    }

#pragma unroll
    for (int i = 0; i < 2; i++) {
        int m = m0 + ty * 2 + i;
#pragma unroll
        for (int j = 0; j < 4; j++) {
            int n = tx * 4 + j;
            float v = acc[i][j] + bias[n];
            float t = tanhf(v) * PI_F;
            float sn, cs;
            sincosf(t, &sn, &cs);
            int bb = m / cL, l = m % cL;
            int kbank = n >> 4, p = n & 15;
            size_t base = ((size_t)(bb * cK + kbank) * cL + l) * cF;
            C[base + p] = cs;
            C[base + cP + p] = sn;
        }
    }
}

// ------------- chunk states via tf32 mma: state = Mf^T @ V -----------------
__global__ __launch_bounds__(256) void chunk_mma_k(
    const float* __restrict__ mfeat, const float* __restrict__ V,
    float* __restrict__ state)
{
    constexpr int SMH = 40;
    constexpr int SVW = 136;
    __shared__ uint32_t sMf[cCH * SMH];
    __shared__ uint32_t sV[cCH * SVW];
    const int ci = blockIdx.x, bk = blockIdx.y;
    const int bb = bk >> 2, kk2 = bk & 3;
    const int tid = threadIdx.x;
    const int warp = tid >> 5, lane = tid & 31;
    const int gid = lane >> 2, tig = lane & 3;

    const size_t featBase = ((size_t)(bb * cK + kk2) * cL + (size_t)ci * cCH) * cF;
#pragma unroll
    for (int r = 0; r < 2; r++) {
        int idx4 = tid + r * 256;
        int row = idx4 >> 3, q = idx4 & 7;
        float4 a4 = *reinterpret_cast<const float4*>(&mfeat[featBase + (size_t)row * cF + q * 4]);
        uint32_t* s = &sMf[row * SMH + q * 4];
        s[0] = f2tf(a4.x); s[1] = f2tf(a4.y); s[2] = f2tf(a4.z); s[3] = f2tf(a4.w);
    }
    const size_t vBase = ((size_t)(bb * cL) + (size_t)ci * cCH) * cD;
    const size_t stBase = (((size_t)(bb * cK + kk2) * cNC + ci) * cF) * cD;

    for (int dh = 0; dh < 2; dh++) {
        if (dh) __syncthreads();
#pragma unroll
        for (int r = 0; r < 8; r++) {
            int idx4 = tid + r * 256;
            int row = idx4 >> 5, q = idx4 & 31;
            float4 v4 = *reinterpret_cast<const float4*>(&V[vBase + (size_t)row * cD + dh * 128 + q * 4]);
            uint32_t* s = &sV[row * SVW + q * 4];
            s[0] = f2tf(v4.x); s[1] = f2tf(v4.y); s[2] = f2tf(v4.z); s[3] = f2tf(v4.w);
        }
        __syncthreads();

        float acc[2][2][4];
#pragma unroll
        for (int i = 0; i < 2; i++)
#pragma unroll
            for (int j = 0; j < 2; j++)
#pragma unroll
                for (int r = 0; r < 4; r++) acc[i][j][r] = 0.f;

#pragma unroll
        for (int ks = 0; ks < 8; ks++) {
            int kk = ks * 8;
            uint32_t a[2][4], b[2][2];
#pragma unroll
            for (int i = 0; i < 2; i++) {
                int mb = i * 16;
                a[i][0] = sMf[(kk + tig) * SMH + mb + gid];
                a[i][1] = sMf[(kk + tig) * SMH + mb + gid + 8];
                a[i][2] = sMf[(kk + tig + 4) * SMH + mb + gid];
                a[i][3] = sMf[(kk + tig + 4) * SMH + mb + gid + 8];
            }
#pragma unroll
            for (int j = 0; j < 2; j++) {
                int nb = warp * 16 + j * 8;
                b[j][0] = sV[(kk + tig) * SVW + nb + gid];
                b[j][1] = sV[(kk + tig + 4) * SVW + nb + gid];
            }
#pragma unroll
            for (int i = 0; i < 2; i++)
#pragma unroll
                for (int j = 0; j < 2; j++) mma_tf32(acc[i][j], a[i], b[j]);
        }

#pragma unroll
        for (int i = 0; i < 2; i++)
#pragma unroll
            for (int j = 0; j < 2; j++)
#pragma unroll
                for (int r = 0; r < 4; r++) {
                    int f = i * 16 + gid + ((r >= 2) ? 8 : 0);
                    int d = dh * 128 + warp * 16 + j * 8 + tig * 2 + (r & 1);
                    state[stBase + (size_t)f * cD + d] = acc[i][j][r];
                }
    }
}

// ------------- exclusive prefix scan, MLP-batched loads --------------------
__global__ __launch_bounds__(256) void scan_k(float* __restrict__ state)
{
    int u = blockIdx.x * 256 + threadIdx.x;
    if (u >= cB * cK * cF * cD) return;
    int fd = u & (cF * cD - 1);
    int bk = u >> 13;
    float* base = state + (size_t)bk * cNC * cF * cD + fd;
    float v[cNC];
#pragma unroll
    for (int ci = 0; ci < cNC; ci++)
        v[ci] = base[(size_t)ci * cF * cD];
    float run = 0.f;
#pragma unroll
    for (int ci = 0; ci < cNC; ci++) {
        base[(size_t)ci * cF * cD] = run;
        run += v[ci];
    }
}

// ------------- retrieval via tf32 mma: R = Qf@S + tril(Qf@Mf^T)@V ----------
__global__ __launch_bounds__(256) void retrieve_mma_k(
    const float* __restrict__ qfeat, const float* __restrict__ mfeat,
    const float* __restrict__ state, const float* __restrict__ V,
    float* __restrict__ comb)
{
    constexpr int SQ = 36;
    constexpr int SAs = 68;
    constexpr int SB = 72;
    __shared__ uint32_t sQ[64 * SQ];
    __shared__ uint32_t sA[64 * SAs];
    __shared__ uint32_t sB[64 * SB];

    const int ci = blockIdx.x;
    const int bk = blockIdx.y;
    const int bb = bk >> 2, kb = bk & 3;
    const int tid = threadIdx.x;
    const int warp = tid >> 5, lane = tid & 31;
    const int wm2 = warp >> 2, wn4 = warp & 3;
    const int gid = lane >> 2, tig = lane & 3;

    const size_t featBase = ((size_t)(bb * cK + kb) * cL + (size_t)ci * cCH) * cF;
#pragma unroll
    for (int r = 0; r < 2; r++) {
        int idx4 = tid + r * 256;
        int row = idx4 >> 3, q = idx4 & 7;
        float4 a4 = *reinterpret_cast<const float4*>(&qfeat[featBase + (size_t)row * cF + q * 4]);
        uint32_t* s = &sQ[row * SQ + q * 4];
        s[0] = f2tf(a4.x); s[1] = f2tf(a4.y); s[2] = f2tf(a4.z); s[3] = f2tf(a4.w);
        float4 m4 = *reinterpret_cast<const float4*>(&mfeat[featBase + (size_t)row * cF + q * 4]);
        uint32_t* t = &sB[row * SQ + q * 4];
        t[0] = f2tf(m4.x); t[1] = f2tf(m4.y); t[2] = f2tf(m4.z); t[3] = f2tf(m4.w);
    }
    __syncthreads();

    // A = tril(Qf @ Mf^T)
    {
        float accA[2][2][4];
#pragma unroll
        for (int i = 0; i < 2; i++)
#pragma unroll
            for (int j = 0; j < 2; j++)
#pragma unroll
                for (int r = 0; r < 4; r++) accA[i][j][r] = 0.f;
#pragma unroll
        for (int ks = 0; ks < 4; ks++) {
            int kk = ks * 8;
            uint32_t a[2][4], b[2][2];
#pragma unroll
            for (int i = 0; i < 2; i++) {
                int mb = wm2 * 32 + i * 16;
                a[i][0] = sQ[(mb + gid) * SQ + kk + tig];
                a[i][1] = sQ[(mb + gid + 8) * SQ + kk + tig];
                a[i][2] = sQ[(mb + gid) * SQ + kk + tig + 4];
                a[i][3] = sQ[(mb + gid + 8) * SQ + kk + tig + 4];
            }
#pragma unroll
            for (int j = 0; j < 2; j++) {
                int nb = wn4 * 16 + j * 8;
                b[j][0] = sB[(nb + gid) * SQ + kk + tig];
                b[j][1] = sB[(nb + gid) * SQ + kk + tig + 4];
            }
#pragma unroll
            for (int i = 0; i < 2; i++)
#pragma unroll
                for (int j = 0; j < 2; j++) mma_tf32(accA[i][j], a[i], b[j]);
        }
        __syncthreads();
#pragma unroll
        for (int i = 0; i < 2; i++)
#pragma unroll
            for (int j = 0; j < 2; j++)
#pragma unroll
                for (int r = 0; r < 4; r++) {
                    int m = wm2 * 32 + i * 16 + gid + ((r >= 2) ? 8 : 0);
                    int n = wn4 * 16 + j * 8 + tig * 2 + (r & 1);
                    float v = (n <= m) ? accA[i][j][r] : 0.f;
                    sA[m * SAs + n] = f2tf(v);
                }
    }
    __syncthreads();

    const size_t stBase = (((size_t)(bb * cK + kb) * cNC + ci) * cF) * cD;
    const size_t vBase = ((size_t)(bb * cL) + (size_t)ci * cCH) * cD;

    for (int dh = 0; dh < 4; dh++) {
        __syncthreads();
#pragma unroll
        for (int r = 0; r < 2; r++) {
            int idx4 = tid + r * 256;
            int f = idx4 >> 4, q = idx4 & 15;
            float4 s4 = *reinterpret_cast<const float4*>(&state[stBase + (size_t)f * cD + dh * 64 + q * 4]);
            uint32_t* s = &sB[f * SB + q * 4];
            s[0] = f2tf(s4.x); s[1] = f2tf(s4.y); s[2] = f2tf(s4.z); s[3] = f2tf(s4.w);
        }
        __syncthreads();

        float accO[2][2][4];
#pragma unroll
        for (int i = 0; i < 2; i++)
#pragma unroll
            for (int j = 0; j < 2; j++)
#pragma unroll
                for (int r = 0; r < 4; r++) accO[i][j][r] = 0.f;

#pragma unroll
        for (int ks = 0; ks < 4; ks++) {
            int kk = ks * 8;
            uint32_t a[2][4], b[2][2];
#pragma unroll
            for (int i = 0; i < 2; i++) {
                int mb = wm2 * 32 + i * 16;
                a[i][0] = sQ[(mb + gid) * SQ + kk + tig];
                a[i][1] = sQ[(mb + gid + 8) * SQ + kk + tig];
                a[i][2] = sQ[(mb + gid) * SQ + kk + tig + 4];
                a[i][3] = sQ[(mb + gid + 8) * SQ + kk + tig + 4];
            }
#pragma unroll
            for (int j = 0; j < 2; j++) {
                int nb = wn4 * 16 + j * 8;
                b[j][0] = sB[(kk + tig) * SB + nb + gid];
                b[j][1] = sB[(kk + tig + 4) * SB + nb + gid];
            }
#pragma unroll
            for (int i = 0; i < 2; i++)
#pragma unroll
                for (int j = 0; j < 2; j++) mma_tf32(accO[i][j], a[i], b[j]);
        }
        __syncthreads();
#pragma unroll
        for (int r = 0; r < 4; r++) {
            int idx4 = tid + r * 256;
            int row = idx4 >> 4, q = idx4 & 15;
            float4 v4 = *reinterpret_cast<const float4*>(&V[vBase + (size_t)row * cD + dh * 64 + q * 4]);
            uint32_t* s = &sB[row * SB + q * 4];
            s[0] = f2tf(v4.x); s[1] = f2tf(v4.y); s[2] = f2tf(v4.z); s[3] = f2tf(v4.w);
        }
        __syncthreads();

#pragma unroll
        for (int ks = 0; ks < 8; ks++) {
            int kk = ks * 8;
            uint32_t a[2][4], b[2][2];
#pragma unroll
            for (int i = 0; i < 2; i++) {
                int mb = wm2 * 32 + i * 16;
                a[i][0] = sA[(mb + gid) * SAs + kk + tig];
                a[i][1] = sA[(mb + gid + 8) * SAs + kk + tig];
                a[i][2] = sA[(mb + gid) * SAs + kk + tig + 4];
                a[i][3] = sA[(mb + gid + 8) * SAs + kk + tig + 4];
            }
#pragma unroll
            for (int j = 0; j < 2; j++) {
                int nb = wn4 * 16 + j * 8;
                b[j][0] = sB[(kk + tig) * SB + nb + gid];
                b[j][1] = sB[(kk + tig + 4) * SB + nb + gid];
            }
#pragma unroll
            for (int i = 0; i < 2; i++)
#pragma unroll
                for (int j = 0; j < 2; j++) mma_tf32(accO[i][j], a[i], b[j]);
        }

#pragma unroll
        for (int i = 0; i < 2; i++)
#pragma unroll
            for (int j = 0; j < 2; j++)
#pragma unroll
                for (int r = 0; r < 4; r++) {
                    int ml = wm2 * 32 + i * 16 + gid + ((r >= 2) ? 8 : 0);
                    int nl = wn4 * 16 + j * 8 + tig * 2 + (r & 1);
                    int l = ci * cCH + ml;
                    float sc = rsqrtf(16.f * (float)(l + 1));
                    comb[((size_t)(bb * cL + l)) * cKD + (size_t)kb * cD + dh * 64 + nl] =
                        accO[i][j][r] * sc;
                }
    }
}

// ------------- row LayerNorm (fp32 in, half out), vectorized ----------------
template<int NDIM>
__global__ __launch_bounds__(256) void ln_h_k(
    const float* __restrict__ in, const float* __restrict__ w,
    const float* __restrict__ bsh, __half* __restrict__ out)
{
    const int row = blockIdx.x;
    const float* xp = in + (size_t)row * NDIM;
    constexpr int R = NDIM / 256;
    float vals[R];
    float s = 0.f, s2 = 0.f;
    if constexpr (R == 4) {
        float4 v4 = reinterpret_cast<const float4*>(xp)[threadIdx.x];
        vals[0] = v4.x; vals[1] = v4.y; vals[2] = v4.z; vals[3] = v4.w;
#pragma unroll
        for (int r = 0; r < 4; r++) { s += vals[r]; s2 += vals[r] * vals[r]; }
    } else {
#pragma unroll
        for (int r = 0; r < R; r++) {
            float v = xp[threadIdx.x + r * 256];
            vals[r] = v; s += v; s2 += v * v;
        }
    }
#pragma unroll
    for (int o = 16; o > 0; o >>= 1) {
        s += __shfl_xor_sync(0xffffffffu, s, o);
        s2 += __shfl_xor_sync(0xffffffffu, s2, o);
    }
    __shared__ float rs[8], rs2[8], sm[2];
    int wid = threadIdx.x >> 5, lane = threadIdx.x & 31;
    if (lane == 0) { rs[wid] = s; rs2[wid] = s2; }
    __syncthreads();
    if (threadIdx.x == 0) {
        float a = 0.f, c = 0.f;
        for (int i = 0; i < 8; i++) { a += rs[i]; c += rs2[i]; }
        float mean = a / NDIM;
        float var = c / NDIM - mean * mean;
        sm[0] = mean;
        sm[1] = rsqrtf(fmaxf(var, 0.f) + 1e-5f);
    }
    __syncthreads();
    float mean = sm[0], inv = sm[1];
    __half* op = out + (size_t)row * NDIM;
    if constexpr (R == 4) {
        float4 w4 = reinterpret_cast<const float4*>(w)[threadIdx.x];
        float4 b4 = reinterpret_cast<const float4*>(bsh)[threadIdx.x];
        __half2 h0 = __floats2half2_rn((vals[0] - mean) * inv * w4.x + b4.x,
                                       (vals[1] - mean) * inv * w4.y + b4.y);
        __half2 h1 = __floats2half2_rn((vals[2] - mean) * inv * w4.z + b4.z,
                                       (vals[3] - mean) * inv * w4.w + b4.w);
        uint32_t lo, hi;
        memcpy(&lo, &h0, 4);
        memcpy(&hi, &h1, 4);
        reinterpret_cast<uint2*>(op)[threadIdx.x] = make_uint2(lo, hi);
    } else {
#pragma unroll
        for (int r = 0; r < R; r++) {
            int i = threadIdx.x + r * 256;
            op[i] = __float2half((vals[r] - mean) * inv * w[i] + bsh[i]);
        }
    }
}

// ------------- host orchestration ------------------------------------------
extern "C" void kernel_launch(void* const* d_in, const int* in_sizes, int n_in,
                              void* d_out, int out_size)
{
    const float* x       = (const float*)d_in[0];
    const float* phase_w = (const float*)d_in[1];
    const float* phase_b = (const float*)d_in[2];
    const float* val_w   = (const float*)d_in[3];
    const float* val_b   = (const float*)d_in[4];
    const float* rlnw    = (const float*)d_in[5];
    const float* rlnb    = (const float*)d_in[6];
    const float* r1w     = (const float*)d_in[7];
    const float* r1b     = (const float*)d_in[8];
    const float* r2w     = (const float*)d_in[9];
    const float* r2b     = (const float*)d_in[10];
    const float* quw     = (const float*)d_in[11];
    const float* qub     = (const float*)d_in[12];
    const float* olnw    = (const float*)d_in[13];
    const float* olnb    = (const float*)d_in[14];
    const float* outw    = (const float*)d_in[15];
    const float* outb    = (const float*)d_in[16];
    float* out = (float*)d_out;

    float *V, *Mf, *Qf, *St, *Cb, *Ac, *Q0, *Q1;
    cudaGetSymbolAddress((void**)&V,  g_V);
    cudaGetSymbolAddress((void**)&Mf, g_Mfeat);
    cudaGetSymbolAddress((void**)&Qf, g_Qfeat);
    cudaGetSymbolAddress((void**)&St, g_state);
    cudaGetSymbolAddress((void**)&Cb, g_comb);
    cudaGetSymbolAddress((void**)&Ac, g_acc);
    cudaGetSymbolAddress((void**)&Q0, g_q0);
    cudaGetSymbolAddress((void**)&Q1, g_q1);
    __half *Xh, *Clh, *Hhh, *Rfh, *Q0h, *Q1h, *Alh;
    __half *ValWh, *R1Wh, *R2Wh, *QuWh, *OutWh;
    cudaGetSymbolAddress((void**)&Xh,  g_xh);
    cudaGetSymbolAddress((void**)&Clh, g_Clh);
    cudaGetSymbolAddress((void**)&Hhh, g_Hhh);
    cudaGetSymbolAddress((void**)&Rfh, g_Rfh);
    cudaGetSymbolAddress((void**)&Q0h, g_q0h);
    cudaGetSymbolAddress((void**)&Q1h, g_q1h);
    cudaGetSymbolAddress((void**)&Alh, g_Alh);
    cudaGetSymbolAddress((void**)&ValWh, g_valwh);
    cudaGetSymbolAddress((void**)&R1Wh, g_r1wh);
    cudaGetSymbolAddress((void**)&R2Wh, g_r2wh);
    cudaGetSymbolAddress((void**)&QuWh, g_quwh);
    cudaGetSymbolAddress((void**)&OutWh, g_outwh);

    // memory-side phase features (fp32; independent of conversion)
    phase_gemm_k<<<cM / 32, 256>>>(x, phase_w, phase_b, Mf);
    // convert weights + x to half (vectorized)
    cvt_h_k<<<512, 256>>>(val_w, r1w, r2w, quw, outw, x);
    // values GEMM (fp16 mma) -> fp32 V
    mma_gemm_k<256, 0, false><<<dim3(cD / 64, cM / 128), 256>>>(
        Xh, nullptr, ValWh, val_b, V, nullptr, nullptr, nullptr, cD, 0);
    // chunk states via tf32 mma + scan
    chunk_mma_k<<<dim3(cNC, cB * cK), 256>>>(Mf, V, St);
    scan_k<<<256, 256>>>(St);

    const float* qin = x;
    const __half* qinh = Xh;
    for (int i = 0; i < cI; i++) {
        float* qout = (i & 1) ? Q1 : Q0;
        __half* qouth = (i & 1) ? Q1h : Q0h;
        phase_gemm_k<<<cM / 32, 256>>>(qin, phase_w, phase_b, Qf);
        retrieve_mma_k<<<dim3(cNC, cB * cK), 256>>>(Qf, Mf, St, V, Cb);
        ln_h_k<1024><<<cM, 256>>>(Cb, rlnw + (size_t)i * cKD, rlnb + (size_t)i * cKD, Clh);
        mma_gemm_k<1024, 2, false><<<dim3(cH / 64, cM / 128), 256>>>(
            Clh, nullptr, R1Wh + (size_t)i * cH * cKD, r1b + (size_t)i * cH,
            nullptr, Hhh, nullptr, nullptr, cH, 0);
        mma_gemm_k<512, 3, false><<<dim3(cD / 64, cM / 128), 256>>>(
            Hhh, nullptr, R2Wh + (size_t)i * cD * cH, r2b + (size_t)i * cD,
            nullptr, Rfh, Ac, nullptr, cD, (i == 0) ? 1 : 0);
        mma_gemm_k<512, 4, true><<<dim3(cD / 64, cM / 128), 256>>>(
            qinh, Rfh, QuWh + (size_t)i * cD * cH, qub + (size_t)i * cD,
            qout, qouth, nullptr, qin, cD, 0);
        qin = qout;
        qinh = qouth;
    }

    ln_h_k<256><<<cM, 256>>>(Ac, olnw, olnb, Alh);
    mma_gemm_k<256, 5, false><<<dim3(cD / 64, cM / 128), 256>>>(
        Alh, nullptr, OutWh, outb, out, nullptr, nullptr, x, cD, 0);
}